// round 13
// baseline (speedup 1.0000x reference)
#include <cuda_runtime.h>

// Max pool 2x2 stride 2, NCHW (32,128,224,224) fp32 -> (32,128,112,112)
// HBM-bound streaming: 822MB read + 206MB write — all mandatory, zero reuse.
//
// FINAL — R4 shape, best of 12 measured variants (143.55us wall, 140.4us
// kernel, 7.13 TB/s, 90% DRAM active = practical HBM3e ceiling for this
// 4:1 read/write mix; traffic audit shows zero wasted bytes).
//  - die-after-work grid (25088 blocks x 256 threads): fresh blocks keep
//    L1tex/DRAM queues full (beat persistent single-wave by 8%)
//  - 2 float4 output quads per thread, strided by blockDim inside the block's
//    512-quad chunk -> fully warp-coalesced 16B loads / 16B stores
//  - 8 independent front-batched LDG.E.128 with .cs (evict-first) on both
//    loads and stores (.wb stores and TMA bulk stores both regressed)

#define IW   224
#define IH   224
#define OW   112
#define OH   112
#define OW4  28                       // float4 quads per output row
#define NC   (32 * 128)
#define TOTAL_QUADS (NC * OH * OW4)   // 12,845,056 = 512 * 25088

__device__ __forceinline__ void decode(int p, const float* __restrict__ in,
                                       const float4** r0, const float4** r1) {
    const int ow4 = p % OW4;
    const int t1  = p / OW4;
    const int oh  = t1 % OH;
    const int nc  = t1 / OH;
    const long long base = (long long)nc * (IH * IW) + (long long)(2 * oh) * IW + 8 * ow4;
    *r0 = reinterpret_cast<const float4*>(in + base);
    *r1 = reinterpret_cast<const float4*>(in + base + IW);
}

__device__ __forceinline__ float4 fmax4(float4 t0, float4 t1, float4 u0, float4 u1) {
    float4 r;
    r.x = fmaxf(fmaxf(t0.x, t0.y), fmaxf(u0.x, u0.y));
    r.y = fmaxf(fmaxf(t0.z, t0.w), fmaxf(u0.z, u0.w));
    r.z = fmaxf(fmaxf(t1.x, t1.y), fmaxf(u1.x, u1.y));
    r.w = fmaxf(fmaxf(t1.z, t1.w), fmaxf(u1.z, u1.w));
    return r;
}

__global__ __launch_bounds__(256, 8)
void pool2d_kernel(const float* __restrict__ in, float4* __restrict__ out) {
    // block covers 512 consecutive quads; thread t does quads t and t+256
    const int pA = blockIdx.x * 512 + threadIdx.x;
    const int pB = pA + 256;

    const float4 *a_r0, *a_r1, *b_r0, *b_r1;
    decode(pA, in, &a_r0, &a_r1);
    decode(pB, in, &b_r0, &b_r1);

    // 8 independent loads, front-batched, evict-first (single touch)
    const float4 a00 = __ldcs(a_r0);  const float4 a01 = __ldcs(a_r0 + 1);
    const float4 a10 = __ldcs(a_r1);  const float4 a11 = __ldcs(a_r1 + 1);
    const float4 b00 = __ldcs(b_r0);  const float4 b01 = __ldcs(b_r0 + 1);
    const float4 b10 = __ldcs(b_r1);  const float4 b11 = __ldcs(b_r1 + 1);

    __stcs(out + pA, fmax4(a00, a01, a10, a11));
    __stcs(out + pB, fmax4(b00, b01, b10, b11));
}

extern "C" void kernel_launch(void* const* d_in, const int* in_sizes, int n_in,
                              void* d_out, int out_size) {
    const float* x = (const float*)d_in[0];
    float4* out = (float4*)d_out;

    const int blocks  = TOTAL_QUADS / 512;   // 25088, no tail
    const int threads = 256;

    pool2d_kernel<<<blocks, threads>>>(x, out);
}

// round 14
// speedup vs baseline: 1.0011x; 1.0011x over previous
#include <cuda_runtime.h>

// Max pool 2x2 stride 2, NCHW (32,128,224,224) fp32 -> (32,128,112,112)
// HBM-bound streaming: 822MB read + 206MB write — all mandatory, zero reuse.
//
// R14: R4 optimum shape + .lu (last-use) loads instead of .cs — line is
// invalidated right after the read, freeing L2 tags instantly for the dirty
// output stream. Last untested cache-policy cell; everything else measured:
//   shape matrix (MLP 4/8/16, occ 33-92%, 128/256 thr, grids 12.5k-100k):
//     all 140+-0.5us kernel / 90% DRAM
//   failed: persistent (-8%), TMA bulk store (-6%), .wb stores (-2%),
//           L2::256B (-1%); neutral: 256-bit ld/st, 32-bit addressing.

#define IW   224
#define IH   224
#define OW   112
#define OH   112
#define OW4  28                       // float4 quads per output row
#define NC   (32 * 128)
#define TOTAL_QUADS (NC * OH * OW4)   // 12,845,056 = 512 * 25088

__device__ __forceinline__ void decode(int p, const float* __restrict__ in,
                                       const float4** r0, const float4** r1) {
    const int ow4 = p % OW4;
    const int t1  = p / OW4;
    const int oh  = t1 % OH;
    const int nc  = t1 / OH;
    const long long base = (long long)nc * (IH * IW) + (long long)(2 * oh) * IW + 8 * ow4;
    *r0 = reinterpret_cast<const float4*>(in + base);
    *r1 = reinterpret_cast<const float4*>(in + base + IW);
}

__device__ __forceinline__ float4 fmax4(float4 t0, float4 t1, float4 u0, float4 u1) {
    float4 r;
    r.x = fmaxf(fmaxf(t0.x, t0.y), fmaxf(u0.x, u0.y));
    r.y = fmaxf(fmaxf(t0.z, t0.w), fmaxf(u0.z, u0.w));
    r.z = fmaxf(fmaxf(t1.x, t1.y), fmaxf(u1.x, u1.y));
    r.w = fmaxf(fmaxf(t1.z, t1.w), fmaxf(u1.z, u1.w));
    return r;
}

__global__ __launch_bounds__(256, 8)
void pool2d_kernel(const float* __restrict__ in, float4* __restrict__ out) {
    // block covers 512 consecutive quads; thread t does quads t and t+256
    const int pA = blockIdx.x * 512 + threadIdx.x;
    const int pB = pA + 256;

    const float4 *a_r0, *a_r1, *b_r0, *b_r1;
    decode(pA, in, &a_r0, &a_r1);
    decode(pB, in, &b_r0, &b_r1);

    // 8 independent loads, front-batched, last-use (invalidate after read)
    const float4 a00 = __ldlu(a_r0);  const float4 a01 = __ldlu(a_r0 + 1);
    const float4 a10 = __ldlu(a_r1);  const float4 a11 = __ldlu(a_r1 + 1);
    const float4 b00 = __ldlu(b_r0);  const float4 b01 = __ldlu(b_r0 + 1);
    const float4 b10 = __ldlu(b_r1);  const float4 b11 = __ldlu(b_r1 + 1);

    __stcs(out + pA, fmax4(a00, a01, a10, a11));
    __stcs(out + pB, fmax4(b00, b01, b10, b11));
}

extern "C" void kernel_launch(void* const* d_in, const int* in_sizes, int n_in,
                              void* d_out, int out_size) {
    const float* x = (const float*)d_in[0];
    float4* out = (float4*)d_out;

    const int blocks  = TOTAL_QUADS / 512;   // 25088, no tail
    const int threads = 256;

    pool2d_kernel<<<blocks, threads>>>(x, out);
}

// round 15
// speedup vs baseline: 1.0111x; 1.0100x over previous
#include <cuda_runtime.h>

// Max pool 2x2 stride 2, NCHW (32,128,224,224) fp32 -> (32,128,112,112)
// HBM-bound streaming: 822MB read + 206MB write — all mandatory, zero reuse.
//
// FINAL kernel (best of 14 measured variants; wall 143.55us, kernel ~140.4us,
// 7.13 TB/s = 90% DRAM active — the practical HBM3e ceiling for a 4:1 R/W mix;
// traffic audit confirms zero wasted bytes).
//
// Shape (R4), chosen by measurement:
//  - die-after-work grid, 25088 blocks x 256 threads: fresh blocks with
//    front-batched loads keep the L1tex/DRAM queues full
//    (persistent single-wave regressed 8%)
//  - 2 float4 output quads per thread, strided by blockDim within the block's
//    512-quad chunk -> fully warp-coalesced 16B loads / 16B stores, no tail
//  - 8 independent front-batched LDG.E.128 per thread (MLP_p1=8; deeper MLP
//    measured neutral)
//  - .cs evict-first on BOTH loads and stores (.lu loads neutral; .wb stores
//    -2%; TMA bulk stores -6%; L2::256B hint -1%)

#define IW   224
#define IH   224
#define OW   112
#define OH   112
#define OW4  28                       // float4 quads per output row
#define NC   (32 * 128)
#define TOTAL_QUADS (NC * OH * OW4)   // 12,845,056 = 512 * 25088

__device__ __forceinline__ void decode(int p, const float* __restrict__ in,
                                       const float4** r0, const float4** r1) {
    const int ow4 = p % OW4;
    const int t1  = p / OW4;
    const int oh  = t1 % OH;
    const int nc  = t1 / OH;
    const long long base = (long long)nc * (IH * IW) + (long long)(2 * oh) * IW + 8 * ow4;
    *r0 = reinterpret_cast<const float4*>(in + base);
    *r1 = reinterpret_cast<const float4*>(in + base + IW);
}

__device__ __forceinline__ float4 fmax4(float4 t0, float4 t1, float4 u0, float4 u1) {
    float4 r;
    r.x = fmaxf(fmaxf(t0.x, t0.y), fmaxf(u0.x, u0.y));
    r.y = fmaxf(fmaxf(t0.z, t0.w), fmaxf(u0.z, u0.w));
    r.z = fmaxf(fmaxf(t1.x, t1.y), fmaxf(u1.x, u1.y));
    r.w = fmaxf(fmaxf(t1.z, t1.w), fmaxf(u1.z, u1.w));
    return r;
}

__global__ __launch_bounds__(256, 8)
void pool2d_kernel(const float* __restrict__ in, float4* __restrict__ out) {
    // block covers 512 consecutive quads; thread t does quads t and t+256
    const int pA = blockIdx.x * 512 + threadIdx.x;
    const int pB = pA + 256;

    const float4 *a_r0, *a_r1, *b_r0, *b_r1;
    decode(pA, in, &a_r0, &a_r1);
    decode(pB, in, &b_r0, &b_r1);

    // 8 independent loads, front-batched, evict-first (single touch)
    const float4 a00 = __ldcs(a_r0);  const float4 a01 = __ldcs(a_r0 + 1);
    const float4 a10 = __ldcs(a_r1);  const float4 a11 = __ldcs(a_r1 + 1);
    const float4 b00 = __ldcs(b_r0);  const float4 b01 = __ldcs(b_r0 + 1);
    const float4 b10 = __ldcs(b_r1);  const float4 b11 = __ldcs(b_r1 + 1);

    __stcs(out + pA, fmax4(a00, a01, a10, a11));
    __stcs(out + pB, fmax4(b00, b01, b10, b11));
}

extern "C" void kernel_launch(void* const* d_in, const int* in_sizes, int n_in,
                              void* d_out, int out_size) {
    const float* x = (const float*)d_in[0];
    float4* out = (float4*)d_out;

    const int blocks  = TOTAL_QUADS / 512;   // 25088, no tail
    const int threads = 256;

    pool2d_kernel<<<blocks, threads>>>(x, out);
}